// round 5
// baseline (speedup 1.0000x reference)
#include <cuda_runtime.h>
#include <cstdint>

#define DM 1024
#define DN 4096
#define BB 2
#define TT 4096
#define MTOT 8192   // BB*TT

// ---------------- scratch (device globals; no allocation allowed) ----------
// g_scr[m*DN+n] = {decay, update, g, h}  (512 MB)
__device__ float4 g_scr[33554432];
// g_y: dual use. Phase 1 (prepass+proj): tf32-rounded X (8.4M floats) then
// 4 rounded W's (4x4.19M). Phase 2 (scan+gemm2): y[m*DN+n] (33.5M floats).
__device__ float  g_y[33554432];
__device__ float  g_wout[4194304];   // tf32-rounded W_out [DM=1024, DN=4096]

#define RX_OFF 0
#define RW_OFF 8388608
#define RW_SZ  4194304

// ---------------- helpers ---------------------------------------------------
__device__ __forceinline__ uint32_t smem_u32(const void* p) {
    uint32_t a;
    asm("{ .reg .u64 t; cvta.to.shared.u64 t, %1; cvt.u32.u64 %0, t; }" : "=r"(a) : "l"(p));
    return a;
}
__device__ __forceinline__ float tf32r(float x) {
    uint32_t u;
    asm("cvt.rna.tf32.f32 %0, %1;" : "=r"(u) : "f"(x));
    return __uint_as_float(u);
}

#define CPA16(dst, src) asm volatile("cp.async.cg.shared.global [%0], [%1], 16;" :: "r"(dst), "l"(src) : "memory")
#define CPA_COMMIT()    asm volatile("cp.async.commit_group;" ::: "memory")
#define CPA_WAIT0()     asm volatile("cp.async.wait_group 0;" ::: "memory")
#define CPA_WAIT1()     asm volatile("cp.async.wait_group 1;" ::: "memory")

// m16n8k8 tf32 mma: A row-major (4 regs), B col-major (2 regs), C fp32 (4 regs)
__device__ __forceinline__ void mma8(float* c, const uint32_t* a, uint32_t b0, uint32_t b1) {
    asm volatile("mma.sync.aligned.m16n8k8.row.col.f32.tf32.tf32.f32 "
                 "{%0,%1,%2,%3}, {%4,%5,%6,%7}, {%8,%9}, {%0,%1,%2,%3};"
                 : "+f"(c[0]), "+f"(c[1]), "+f"(c[2]), "+f"(c[3])
                 : "r"(a[0]), "r"(a[1]), "r"(a[2]), "r"(a[3]), "r"(b0), "r"(b1));
}

// ==================== Kernel 0: tf32-round inputs into scratch ==============
// float4 chunks: X 2,097,152 | 4xW 4,194,304 | Wout 1,048,576  => 7,340,032
__global__ void __launch_bounds__(256)
prepass_kernel(const float* __restrict__ X,
               const float* __restrict__ Wm, const float* __restrict__ Wg,
               const float* __restrict__ Wmod, const float* __restrict__ Wd,
               const float* __restrict__ Wout) {
    int idx = blockIdx.x * 256 + threadIdx.x;
    const float4* src;
    float4* dst;
    if (idx < 2097152) {                           // X: 8,388,608 floats
        src = (const float4*)X + idx;
        dst = (float4*)(g_y + RX_OFF) + idx;
    } else if (idx < 6291456) {                    // 4 x W: 4,194,304 floats each
        int t = idx - 2097152;
        int w = t >> 20;                           // /1,048,576
        int o = t & 1048575;
        const float* W = (w == 0) ? Wm : (w == 1) ? Wg : (w == 2) ? Wmod : Wd;
        src = (const float4*)W + o;
        dst = (float4*)(g_y + RW_OFF + (size_t)w * RW_SZ) + o;
    } else {                                       // W_out: 4,194,304 floats
        int o = idx - 6291456;                     // [0, 1,048,576)
        src = (const float4*)Wout + o;
        dst = (float4*)g_wout + o;
    }
    float4 v = *src;
    v.x = tf32r(v.x); v.y = tf32r(v.y); v.z = tf32r(v.z); v.w = tf32r(v.w);
    *dst = v;
}

// ==================== Kernel 1: fused 4-way projection + pointwise ==========
// CTA: 256 thr (8 warps: 4 m x 2 n). Tile 128m x 64n x 4 weights. KT=32.
// SMEM per buffer: X 128x36 fl (18432 B) + W 4x64x36 fl (36864 B) = 55296 B.
#define P_BUF   55296
#define P_PAR   (2 * P_BUF)          // 110592: bd[64], Aa[64], sw[64]
#define P_SMEM  (P_PAR + 768)
#define XSTR    36                    // padded row stride (floats)

__device__ __forceinline__ void proj_load(uint32_t sb, int buf, int k0, int m0, int n0, int tid) {
    uint32_t base = sb + buf * P_BUF;
    const float* rX = g_y + RX_OFF;
    #pragma unroll
    for (int i = 0; i < 4; i++) {                 // X: 1024 16B-chunks
        int ch = tid + i * 256;
        int r = ch >> 3, c = ch & 7;
        CPA16(base + r * 144 + c * 16, rX + (size_t)(m0 + r) * 1024 + k0 + c * 4);
    }
    #pragma unroll
    for (int i = 0; i < 8; i++) {                 // W: 2048 16B-chunks
        int ch = tid + i * 256;
        int w = ch >> 9, r = (ch >> 3) & 63, c = ch & 7;
        CPA16(base + 18432 + w * 9216 + r * 144 + c * 16,
              g_y + RW_OFF + (size_t)w * RW_SZ + (size_t)(n0 + r) * 1024 + k0 + c * 4);
    }
}

__global__ void __launch_bounds__(256, 1)
proj_kernel(const float* __restrict__ bdel, const float* __restrict__ Alog,
            const float* __restrict__ swl) {
    extern __shared__ char smem[];
    uint32_t sb = smem_u32(smem);
    int tid = threadIdx.x, wid = tid >> 5, lane = tid & 31;
    int wm = wid & 3, wn = wid >> 2;
    int tq = lane >> 2, tr = lane & 3;
    int m0 = blockIdx.x * 128;
    int n0 = blockIdx.y * 64;

    if (tid < 64) {
        int n = n0 + tid;
        ((float*)(smem + P_PAR))[tid]       = bdel[n];
        ((float*)(smem + P_PAR))[64 + tid]  = -__expf(Alog[n]);
        float sl = swl[n];
        ((float*)(smem + P_PAR))[128 + tid] = 1.f / (1.f + __expf(-sl));
    }

    float acc[4][2][4][4];
    #pragma unroll
    for (int w = 0; w < 4; w++)
        #pragma unroll
        for (int i = 0; i < 2; i++)
            #pragma unroll
            for (int j = 0; j < 4; j++)
                #pragma unroll
                for (int c = 0; c < 4; c++) acc[w][i][j][c] = 0.f;

    proj_load(sb, 0, 0, m0, n0, tid);
    CPA_COMMIT();

    for (int kt = 0; kt < 32; kt++) {
        if (kt + 1 < 32) {
            proj_load(sb, (kt + 1) & 1, (kt + 1) * 32, m0, n0, tid);
            CPA_COMMIT();
            CPA_WAIT1();
        } else {
            CPA_WAIT0();
        }
        __syncthreads();

        int buf = kt & 1;
        const uint32_t* sx = (const uint32_t*)(smem + buf * P_BUF);
        const uint32_t* sw = (const uint32_t*)(smem + buf * P_BUF + 18432);
        #pragma unroll
        for (int ks = 0; ks < 4; ks++) {
            uint32_t a[2][4];
            #pragma unroll
            for (int i = 0; i < 2; i++) {
                int r0 = wm * 32 + i * 16 + tq;
                int kb = ks * 8 + tr;
                a[i][0] = sx[r0 * XSTR + kb];
                a[i][1] = sx[(r0 + 8) * XSTR + kb];
                a[i][2] = sx[r0 * XSTR + kb + 4];
                a[i][3] = sx[(r0 + 8) * XSTR + kb + 4];
            }
            #pragma unroll
            for (int w = 0; w < 4; w++) {
                #pragma unroll
                for (int j = 0; j < 4; j++) {
                    int nn = wn * 32 + j * 8 + tq;
                    const uint32_t* bp = sw + w * 2304 + nn * XSTR + ks * 8 + tr;
                    uint32_t b0 = bp[0], b1 = bp[4];
                    mma8(acc[w][0][j], a[0], b0, b1);
                    mma8(acc[w][1][j], a[1], b0, b1);
                }
            }
        }
        __syncthreads();
    }

    // ---- fused pointwise epilogue -> g_scr ----
    const float* bd  = (const float*)(smem + P_PAR);
    const float* Aa  = bd + 64;
    const float* sws = bd + 128;
    #pragma unroll
    for (int i = 0; i < 2; i++) {
        #pragma unroll
        for (int half = 0; half < 2; half++) {
            int m = m0 + wm * 32 + i * 16 + tq + half * 8;
            float4* orow = g_scr + (size_t)m * DN + n0;
            #pragma unroll
            for (int j = 0; j < 4; j++) {
                #pragma unroll
                for (int cc = 0; cc < 2; cc++) {
                    int ci = half * 2 + cc;
                    int nl = wn * 32 + j * 8 + tr * 2 + cc;
                    float raw = acc[0][i][j][ci];
                    float gp  = acc[1][i][j][ci];
                    float mp  = acc[2][i][j][ci];
                    float dp  = acc[3][i][j][ci];
                    float gate = 1.f / (1.f + __expf(-gp));
                    float mod  = tanhf(mp);
                    float z = dp + bd[nl];
                    float splus = (z > 15.f) ? z : log1pf(__expf(z));
                    float decay = __expf(splus * Aa[nl]);
                    float u = (1.f - decay) * gate * tanhf(raw);
                    float gl = 0.5f * raw * (1.f + erff(raw * 0.7071067811865475f));
                    float sw_ = sws[nl];
                    float opm = 1.f + mod;
                    orow[nl] = make_float4(decay, u, (1.f - sw_) * gl * opm, sw_ * opm);
                }
            }
        }
    }
}

// ==================== Kernel 2: sequential scan over T ======================
__global__ void __launch_bounds__(64)
scan_kernel(const float* __restrict__ st_in, float* __restrict__ st_out, int write_state) {
    int ch = blockIdx.x * 64 + threadIdx.x;          // 8192 channels
    int b = ch >> 12;
    size_t base = ((size_t)b * TT) * DN + (ch & 4095);
    const float4* p = g_scr + base;
    float* yo = g_y + base;
    float s = st_in[ch];
    for (int t0 = 0; t0 < TT; t0 += 16) {
        float4 v[16];
        #pragma unroll
        for (int i = 0; i < 16; i++) v[i] = p[(size_t)(t0 + i) * DN];
        #pragma unroll
        for (int i = 0; i < 16; i++) {
            s = fmaf(v[i].x, s, v[i].y);
            yo[(size_t)(t0 + i) * DN] = tf32r(fmaf(v[i].w, s, v[i].z));
        }
    }
    if (write_state) st_out[ch] = s;
}

// ==================== Kernel 3: output GEMM y @ Wout^T ======================
// CTA 256 thr, tile 128m x 64n, KT=32, 128 k-iters.
// SMEM buffer: A 128x36 (18432 B) + B 64x36 (9216 B) = 27648 B.
#define G_BUF  27648
#define G_SMEM (2 * G_BUF)

__device__ __forceinline__ void gem2_load(uint32_t sb, int buf, int k0, int m0, int n0, int tid) {
    uint32_t base = sb + buf * G_BUF;
    #pragma unroll
    for (int i = 0; i < 4; i++) {                 // y: 1024 chunks
        int ch = tid + i * 256;
        int r = ch >> 3, c = ch & 7;
        CPA16(base + r * 144 + c * 16, g_y + (size_t)(m0 + r) * 4096 + k0 + c * 4);
    }
    #pragma unroll
    for (int i = 0; i < 2; i++) {                 // Wout: 512 chunks
        int ch = tid + i * 256;
        int r = ch >> 3, c = ch & 7;
        CPA16(base + 18432 + r * 144 + c * 16, g_wout + (size_t)(n0 + r) * 4096 + k0 + c * 4);
    }
}

__global__ void __launch_bounds__(256, 1)
gemm2_kernel(float* __restrict__ out) {
    extern __shared__ char smem[];
    uint32_t sb = smem_u32(smem);
    int tid = threadIdx.x, wid = tid >> 5, lane = tid & 31;
    int wm = wid & 3, wn = wid >> 2;
    int tq = lane >> 2, tr = lane & 3;
    int m0 = blockIdx.x * 128;
    int n0 = blockIdx.y * 64;

    float acc[2][4][4];
    #pragma unroll
    for (int i = 0; i < 2; i++)
        #pragma unroll
        for (int j = 0; j < 4; j++)
            #pragma unroll
            for (int c = 0; c < 4; c++) acc[i][j][c] = 0.f;

    gem2_load(sb, 0, 0, m0, n0, tid);
    CPA_COMMIT();

    for (int kt = 0; kt < 128; kt++) {
        if (kt + 1 < 128) {
            gem2_load(sb, (kt + 1) & 1, (kt + 1) * 32, m0, n0, tid);
            CPA_COMMIT();
            CPA_WAIT1();
        } else {
            CPA_WAIT0();
        }
        __syncthreads();

        int buf = kt & 1;
        const uint32_t* sa = (const uint32_t*)(smem + buf * G_BUF);
        const uint32_t* sw = (const uint32_t*)(smem + buf * G_BUF + 18432);
        #pragma unroll
        for (int ks = 0; ks < 4; ks++) {
            uint32_t a[2][4];
            #pragma unroll
            for (int i = 0; i < 2; i++) {
                int r0 = wm * 32 + i * 16 + tq;
                int kb = ks * 8 + tr;
                a[i][0] = sa[r0 * XSTR + kb];
                a[i][1] = sa[(r0 + 8) * XSTR + kb];
                a[i][2] = sa[r0 * XSTR + kb + 4];
                a[i][3] = sa[(r0 + 8) * XSTR + kb + 4];
            }
            #pragma unroll
            for (int j = 0; j < 4; j++) {
                int nn = wn * 32 + j * 8 + tq;
                const uint32_t* bp = sw + nn * XSTR + ks * 8 + tr;
                uint32_t b0 = bp[0], b1 = bp[4];
                mma8(acc[0][j], a[0], b0, b1);
                mma8(acc[1][j], a[1], b0, b1);
            }
        }
        __syncthreads();
    }

    #pragma unroll
    for (int i = 0; i < 2; i++) {
        #pragma unroll
        for (int half = 0; half < 2; half++) {
            int m = m0 + wm * 32 + i * 16 + tq + half * 8;
            float* orow = out + (size_t)m * DM + n0;
            #pragma unroll
            for (int j = 0; j < 4; j++) {
                int nl = wn * 32 + j * 8 + tr * 2;
                float2 v = make_float2(acc[i][j][half * 2], acc[i][j][half * 2 + 1]);
                *(float2*)(orow + nl) = v;
            }
        }
    }
}

// ==================== launch ================================================
extern "C" void kernel_launch(void* const* d_in, const int* in_sizes, int n_in,
                              void* d_out, int out_size) {
    const float* x    = (const float*)d_in[0];
    const float* st   = (const float*)d_in[1];
    const float* Wm   = (const float*)d_in[2];
    const float* Wg   = (const float*)d_in[3];
    const float* Wmod = (const float*)d_in[4];
    const float* Wout = (const float*)d_in[5];
    const float* Wd   = (const float*)d_in[6];
    const float* bdel = (const float*)d_in[7];
    const float* Alog = (const float*)d_in[8];
    const float* swl  = (const float*)d_in[9];
    float* out = (float*)d_out;

    cudaFuncSetAttribute(proj_kernel,  cudaFuncAttributeMaxDynamicSharedMemorySize, P_SMEM);
    cudaFuncSetAttribute(gemm2_kernel, cudaFuncAttributeMaxDynamicSharedMemorySize, G_SMEM);

    prepass_kernel<<<28672, 256>>>(x, Wm, Wg, Wmod, Wd, Wout);

    proj_kernel<<<dim3(64, 64), 256, P_SMEM>>>(bdel, Alog, swl);

    int has_state = (out_size >= MTOT * DM + BB * DN) ? 1 : 0;
    scan_kernel<<<128, 64>>>(st, out + (size_t)MTOT * DM, has_state);

    gemm2_kernel<<<dim3(64, 16), 256, G_SMEM>>>(out);
}

// round 6
// speedup vs baseline: 1.0293x; 1.0293x over previous
#include <cuda_runtime.h>
#include <cstdint>

#define DM 1024
#define DN 4096
#define BB 2
#define TT 4096
#define MTOT 8192   // BB*TT

// ---------------- scratch (device globals; no allocation allowed) ----------
// g_scr[m*DN+n] = {decay, update, g, h}  (512 MB)
__device__ float4 g_scr[33554432];
// g_y: phase 1: tf32-rounded X (8.4M floats) + 4 rounded W's (W_cat, 16.8M).
//      phase 2 (scan onward): y[m*DN+n] (33.5M floats).
__device__ float  g_y[33554432];
__device__ float  g_wout[4194304];     // tf32-rounded W_out [1024, 4096]
__device__ float  g_raw[134217728];    // proj raw output [8192, 16384] (512 MB)

#define RX_OFF 0
#define RW_OFF 8388608
#define RW_SZ  4194304

// ---------------- helpers ---------------------------------------------------
__device__ __forceinline__ uint32_t smem_u32(const void* p) {
    uint32_t a;
    asm("{ .reg .u64 t; cvta.to.shared.u64 t, %1; cvt.u32.u64 %0, t; }" : "=r"(a) : "l"(p));
    return a;
}
__device__ __forceinline__ float tf32r(float x) {
    uint32_t u;
    asm("cvt.rna.tf32.f32 %0, %1;" : "=r"(u) : "f"(x));
    return __uint_as_float(u);
}

#define CPA16(dst, src) asm volatile("cp.async.cg.shared.global [%0], [%1], 16;" :: "r"(dst), "l"(src) : "memory")
#define CPA_COMMIT()    asm volatile("cp.async.commit_group;" ::: "memory")
#define CPA_WAIT0()     asm volatile("cp.async.wait_group 0;" ::: "memory")
#define CPA_WAIT1()     asm volatile("cp.async.wait_group 1;" ::: "memory")

// m16n8k8 tf32 mma: A row-major (4 regs), B col-major (2 regs), C fp32 (4 regs)
__device__ __forceinline__ void mma8(float* c, const uint32_t* a, uint32_t b0, uint32_t b1) {
    asm volatile("mma.sync.aligned.m16n8k8.row.col.f32.tf32.tf32.f32 "
                 "{%0,%1,%2,%3}, {%4,%5,%6,%7}, {%8,%9}, {%0,%1,%2,%3};"
                 : "+f"(c[0]), "+f"(c[1]), "+f"(c[2]), "+f"(c[3])
                 : "r"(a[0]), "r"(a[1]), "r"(a[2]), "r"(a[3]), "r"(b0), "r"(b1));
}

// ==================== Kernel 0: tf32-round inputs into scratch ==============
// float4 chunks: X 2,097,152 | 4xW 4,194,304 | Wout 1,048,576  => 7,340,032
__global__ void __launch_bounds__(256)
prepass_kernel(const float* __restrict__ X,
               const float* __restrict__ Wm, const float* __restrict__ Wg,
               const float* __restrict__ Wmod, const float* __restrict__ Wd,
               const float* __restrict__ Wout) {
    int idx = blockIdx.x * 256 + threadIdx.x;
    const float4* src;
    float4* dst;
    if (idx < 2097152) {                           // X
        src = (const float4*)X + idx;
        dst = (float4*)(g_y + RX_OFF) + idx;
    } else if (idx < 6291456) {                    // 4 x W -> contiguous W_cat
        int t = idx - 2097152;
        int w = t >> 20;
        int o = t & 1048575;
        const float* W = (w == 0) ? Wm : (w == 1) ? Wg : (w == 2) ? Wmod : Wd;
        src = (const float4*)W + o;
        dst = (float4*)(g_y + RW_OFF + (size_t)w * RW_SZ) + o;
    } else {                                       // W_out: 4,194,304 floats
        int o = idx - 6291456;
        src = (const float4*)Wout + o;
        dst = (float4*)g_wout + o;
    }
    float4 v = *src;
    v.x = tf32r(v.x); v.y = tf32r(v.y); v.z = tf32r(v.z); v.w = tf32r(v.w);
    *dst = v;
}

// ==================== Generic tf32 GEMM: C[M,N] = A[M,K] @ B[N,K]^T =========
// CTA 256 thr (8 warps: 4m x 2n), tile 128m x 128n, KT=32, warp tile 32x64.
// SMEM per stage: A 128x36 fl + B 128x36 fl = 36864 B; 2 stages = 73728 B.
#define XSTR  36
#define GBUF  36864
#define GSMEM (2 * GBUF)

__device__ __forceinline__ void g_load(uint32_t sb, int stage,
                                       const float* __restrict__ A,
                                       const float* __restrict__ B,
                                       int m0, int n0, int k0, int K, int tid) {
    uint32_t base = sb + stage * GBUF;
    #pragma unroll
    for (int i = 0; i < 4; i++) {                 // A: 1024 16B-chunks
        int ch = tid + i * 256;
        int r = ch >> 3, c = ch & 7;
        CPA16(base + r * 144 + c * 16, A + (size_t)(m0 + r) * K + k0 + c * 4);
    }
    #pragma unroll
    for (int i = 0; i < 4; i++) {                 // B: 1024 16B-chunks
        int ch = tid + i * 256;
        int r = ch >> 3, c = ch & 7;
        CPA16(base + 18432 + r * 144 + c * 16, B + (size_t)(n0 + r) * K + k0 + c * 4);
    }
}

__global__ void __launch_bounds__(256, 2)
gemm_kernel(const float* __restrict__ A, const float* __restrict__ B,
            float* __restrict__ C, int K, int N) {
    extern __shared__ char smem[];
    uint32_t sb = smem_u32(smem);
    int tid = threadIdx.x, wid = tid >> 5, lane = tid & 31;
    int wm = wid & 3, wn = wid >> 2;
    int tq = lane >> 2, tr = lane & 3;
    int m0 = blockIdx.x * 128;
    int n0 = blockIdx.y * 128;

    float acc[2][8][4];
    #pragma unroll
    for (int i = 0; i < 2; i++)
        #pragma unroll
        for (int j = 0; j < 8; j++)
            #pragma unroll
            for (int c = 0; c < 4; c++) acc[i][j][c] = 0.f;

    g_load(sb, 0, A, B, m0, n0, 0, K, tid);
    CPA_COMMIT();

    int nkt = K >> 5;
    for (int kt = 0; kt < nkt; kt++) {
        if (kt + 1 < nkt) {
            g_load(sb, (kt + 1) & 1, A, B, m0, n0, (kt + 1) * 32, K, tid);
            CPA_COMMIT();
            CPA_WAIT1();
        } else {
            CPA_WAIT0();
        }
        __syncthreads();

        int stage = kt & 1;
        const uint32_t* sa = (const uint32_t*)(smem + stage * GBUF);
        const uint32_t* sw = (const uint32_t*)(smem + stage * GBUF + 18432);
        #pragma unroll
        for (int ks = 0; ks < 4; ks++) {
            uint32_t a[2][4];
            #pragma unroll
            for (int i = 0; i < 2; i++) {
                int r0 = wm * 32 + i * 16 + tq;
                int kb = ks * 8 + tr;
                a[i][0] = sa[r0 * XSTR + kb];
                a[i][1] = sa[(r0 + 8) * XSTR + kb];
                a[i][2] = sa[r0 * XSTR + kb + 4];
                a[i][3] = sa[(r0 + 8) * XSTR + kb + 4];
            }
            #pragma unroll
            for (int j = 0; j < 8; j++) {
                int nn = wn * 64 + j * 8 + tq;
                const uint32_t* bp = sw + nn * XSTR + ks * 8 + tr;
                uint32_t b0 = bp[0], b1 = bp[4];
                mma8(acc[0][j], a[0], b0, b1);
                mma8(acc[1][j], a[1], b0, b1);
            }
        }
        __syncthreads();
    }

    // store: c0,c1 -> (row tq, cols 2tr..2tr+1); c2,c3 -> row tq+8
    #pragma unroll
    for (int i = 0; i < 2; i++) {
        #pragma unroll
        for (int half = 0; half < 2; half++) {
            int m = m0 + wm * 32 + i * 16 + tq + half * 8;
            float* orow = C + (size_t)m * N + n0;
            #pragma unroll
            for (int j = 0; j < 8; j++) {
                int nl = wn * 64 + j * 8 + tr * 2;
                float2 v = make_float2(acc[i][j][half * 2], acc[i][j][half * 2 + 1]);
                *(float2*)(orow + nl) = v;
            }
        }
    }
}

// ==================== Kernel 2: pointwise epilogue (raw -> g_scr) ===========
__device__ __forceinline__ float4 epi_one(float raw, float gp, float mp, float dpv,
                                          float bd, float al, float sl) {
    float gate = 1.f / (1.f + __expf(-gp));
    float mod  = tanhf(mp);
    float z = dpv + bd;
    float Aa = -__expf(al);
    float splus = (z > 15.f) ? z : log1pf(__expf(z));
    float decay = __expf(splus * Aa);
    float u = (1.f - decay) * gate * tanhf(raw);
    float gl = 0.5f * raw * (1.f + erff(raw * 0.7071067811865475f));
    float sw = 1.f / (1.f + __expf(-sl));
    float opm = 1.f + mod;
    return make_float4(decay, u, (1.f - sw) * gl * opm, sw * opm);
}

__global__ void __launch_bounds__(256)
epi_kernel(const float* __restrict__ bdel, const float* __restrict__ Alog,
           const float* __restrict__ swl) {
    int idx = blockIdx.x * 256 + threadIdx.x;   // 0 .. 8,388,607 (float4 granules)
    int m  = idx >> 10;                          // DN/4 = 1024 granules per row
    int n  = (idx & 1023) << 2;
    const float* rowp = g_raw + (size_t)m * 16384;
    float4 raw = *(const float4*)(rowp + n);
    float4 gp  = *(const float4*)(rowp + 4096 + n);
    float4 mp  = *(const float4*)(rowp + 8192 + n);
    float4 dp  = *(const float4*)(rowp + 12288 + n);
    float4 bd  = *(const float4*)(bdel + n);
    float4 al  = *(const float4*)(Alog + n);
    float4 sl  = *(const float4*)(swl + n);
    float4* dst = g_scr + (size_t)m * DN + n;
    dst[0] = epi_one(raw.x, gp.x, mp.x, dp.x, bd.x, al.x, sl.x);
    dst[1] = epi_one(raw.y, gp.y, mp.y, dp.y, bd.y, al.y, sl.y);
    dst[2] = epi_one(raw.z, gp.z, mp.z, dp.z, bd.z, al.z, sl.z);
    dst[3] = epi_one(raw.w, gp.w, mp.w, dp.w, bd.w, al.w, sl.w);
}

// ==================== Kernel 3: sequential scan over T ======================
__global__ void __launch_bounds__(64)
scan_kernel(const float* __restrict__ st_in, float* __restrict__ st_out, int write_state) {
    int ch = blockIdx.x * 64 + threadIdx.x;          // 8192 channels
    int b = ch >> 12;
    size_t base = ((size_t)b * TT) * DN + (ch & 4095);
    const float4* p = g_scr + base;
    float* yo = g_y + base;
    float s = st_in[ch];
    for (int t0 = 0; t0 < TT; t0 += 16) {
        float4 v[16];
        #pragma unroll
        for (int i = 0; i < 16; i++) v[i] = p[(size_t)(t0 + i) * DN];
        #pragma unroll
        for (int i = 0; i < 16; i++) {
            s = fmaf(v[i].x, s, v[i].y);
            yo[(size_t)(t0 + i) * DN] = tf32r(fmaf(v[i].w, s, v[i].z));
        }
    }
    if (write_state) st_out[ch] = s;
}

// ==================== launch ================================================
extern "C" void kernel_launch(void* const* d_in, const int* in_sizes, int n_in,
                              void* d_out, int out_size) {
    const float* x    = (const float*)d_in[0];
    const float* st   = (const float*)d_in[1];
    const float* Wout = (const float*)d_in[5];
    const float* Wm   = (const float*)d_in[2];
    const float* Wg   = (const float*)d_in[3];
    const float* Wmod = (const float*)d_in[4];
    const float* Wd   = (const float*)d_in[6];
    const float* bdel = (const float*)d_in[7];
    const float* Alog = (const float*)d_in[8];
    const float* swl  = (const float*)d_in[9];
    float* out = (float*)d_out;

    cudaFuncSetAttribute(gemm_kernel, cudaFuncAttributeMaxDynamicSharedMemorySize, GSMEM);

    // device-global scratch pointers (host-side address fetch is graph-safe? no —
    // use cudaGetSymbolAddress which is not an alloc and not capture-hostile)
    static float* p_rx = nullptr;
    static float* p_rw = nullptr;
    static float* p_raw = nullptr;
    static float* p_y = nullptr;
    static float* p_wout = nullptr;
    if (!p_rx) {
        void* tmp;
        cudaGetSymbolAddress(&tmp, g_y);    p_rx = (float*)tmp;
        p_rw = p_rx + RW_OFF;
        p_y  = p_rx;
        cudaGetSymbolAddress(&tmp, g_raw);  p_raw = (float*)tmp;
        cudaGetSymbolAddress(&tmp, g_wout); p_wout = (float*)tmp;
    }

    prepass_kernel<<<28672, 256>>>(x, Wm, Wg, Wmod, Wd, Wout);

    // proj: C[8192,16384] = rX[8192,1024] @ W_cat[16384,1024]^T
    gemm_kernel<<<dim3(64, 128), 256, GSMEM>>>(p_rx, p_rw, p_raw, 1024, 16384);

    epi_kernel<<<32768, 256>>>(bdel, Alog, swl);

    int has_state = (out_size >= MTOT * DM + BB * DN) ? 1 : 0;
    scan_kernel<<<128, 64>>>(st, out + (size_t)MTOT * DM, has_state);

    // out: C[8192,1024] = y[8192,4096] @ Wout[1024,4096]^T
    gemm_kernel<<<dim3(64, 8), 256, GSMEM>>>(p_y, p_wout, out, 4096, 1024);
}

// round 8
// speedup vs baseline: 1.6339x; 1.5874x over previous
#include <cuda_runtime.h>
#include <cuda_fp16.h>
#include <cstdint>

#define DM 1024
#define DN 4096
#define BB 2
#define TT 4096
#define MTOT 8192   // BB*TT

// ---------------- scratch (device globals) ----------------------------------
__device__ __half  g_xh[8388608];      // fp16 X [8192,1024]
__device__ __half  g_wh[16777216];     // fp16 W_cat [16384,1024]
__device__ __half  g_wouth[4194304];   // fp16 W_out [1024,4096]
__device__ float   g_raw[134217728];   // proj raw output [8192,16384] fp32
__device__ float2  g_du[33554432];     // {decay, update} [8192,4096]
__device__ float2  g_gh[33554432];     // {g, h}          [8192,4096]
__device__ __half  g_yh[33554432];     // fp16 y          [8192,4096]

// ---------------- helpers ----------------------------------------------------
__device__ __forceinline__ uint32_t smem_u32(const void* p) {
    uint32_t a;
    asm("{ .reg .u64 t; cvta.to.shared.u64 t, %1; cvt.u32.u64 %0, t; }" : "=r"(a) : "l"(p));
    return a;
}

#define CPA16(dst, src) asm volatile("cp.async.cg.shared.global [%0], [%1], 16;" :: "r"(dst), "l"(src) : "memory")
#define CPA_COMMIT()    asm volatile("cp.async.commit_group;" ::: "memory")
#define CPA_WAIT0()     asm volatile("cp.async.wait_group 0;" ::: "memory")
#define CPA_WAIT1()     asm volatile("cp.async.wait_group 1;" ::: "memory")

// m16n8k16 fp16 mma, fp32 accum: A row-major (4 u32), B col-major (2 u32)
__device__ __forceinline__ void mma16(float* c, const uint32_t* a, uint32_t b0, uint32_t b1) {
    asm volatile("mma.sync.aligned.m16n8k16.row.col.f32.f16.f16.f32 "
                 "{%0,%1,%2,%3}, {%4,%5,%6,%7}, {%8,%9}, {%0,%1,%2,%3};"
                 : "+f"(c[0]), "+f"(c[1]), "+f"(c[2]), "+f"(c[3])
                 : "r"(a[0]), "r"(a[1]), "r"(a[2]), "r"(a[3]), "r"(b0), "r"(b1));
}

// ==================== Kernel 0: fp32 -> fp16 conversion =====================
// float4 granules: X 2,097,152 | W_cat 4,194,304 | Wout 1,048,576 => 7,340,032
__global__ void __launch_bounds__(256)
prepass_kernel(const float* __restrict__ X,
               const float* __restrict__ Wm, const float* __restrict__ Wg,
               const float* __restrict__ Wmod, const float* __restrict__ Wd,
               const float* __restrict__ Wout) {
    int idx = blockIdx.x * 256 + threadIdx.x;
    const float4* src;
    __half2* dst;
    if (idx < 2097152) {
        src = (const float4*)X + idx;
        dst = (__half2*)g_xh + idx * 2;
    } else if (idx < 6291456) {
        int t = idx - 2097152;
        int w = t >> 20;
        int o = t & 1048575;
        const float* W = (w == 0) ? Wm : (w == 1) ? Wg : (w == 2) ? Wmod : Wd;
        src = (const float4*)W + o;
        dst = (__half2*)g_wh + ((size_t)w * 1048576 + o) * 2;
    } else {
        int o = idx - 6291456;
        src = (const float4*)Wout + o;
        dst = (__half2*)g_wouth + o * 2;
    }
    float4 v = *src;
    dst[0] = __floats2half2_rn(v.x, v.y);
    dst[1] = __floats2half2_rn(v.z, v.w);
}

// ==================== fp16 GEMM: C[M,N] = A[M,K] @ B[N,K]^T =================
// CTA 256 thr (8 warps: 4m x 2n), tile 128m x 128n, KT=32 halves, warp 32x64.
// SMEM stage: A 128 x 80B + B 128 x 80B = 20480 B; 2 stages = 40960 B.
#define HSTR  20            // row stride in u32 (40 halves = 80 B)
#define HBUF  20480
#define HSMEM (2 * HBUF)

__device__ __forceinline__ void h_load(uint32_t sb, int stage,
                                       const __half* __restrict__ A,
                                       const __half* __restrict__ B,
                                       int m0, int n0, int k0, int K, int tid) {
    uint32_t base = sb + stage * HBUF;
    #pragma unroll
    for (int i = 0; i < 2; i++) {                 // A: 512 16B-chunks
        int ch = tid + i * 256;
        int r = ch >> 2, c = ch & 3;
        CPA16(base + r * 80 + c * 16, A + (size_t)(m0 + r) * K + k0 + c * 8);
    }
    #pragma unroll
    for (int i = 0; i < 2; i++) {                 // B: 512 16B-chunks
        int ch = tid + i * 256;
        int r = ch >> 2, c = ch & 3;
        CPA16(base + 10240 + r * 80 + c * 16, B + (size_t)(n0 + r) * K + k0 + c * 8);
    }
}

__global__ void __launch_bounds__(256, 2)
gemm_kernel(const __half* __restrict__ A, const __half* __restrict__ B,
            float* __restrict__ C, int K, int N) {
    extern __shared__ char smem[];
    uint32_t sb = smem_u32(smem);
    int tid = threadIdx.x, wid = tid >> 5, lane = tid & 31;
    int wm = wid & 3, wn = wid >> 2;
    int tq = lane >> 2, tr = lane & 3;
    int m0 = blockIdx.y * 128;
    int n0 = blockIdx.x * 128;

    float acc[2][8][4];
    #pragma unroll
    for (int i = 0; i < 2; i++)
        #pragma unroll
        for (int j = 0; j < 8; j++)
            #pragma unroll
            for (int c = 0; c < 4; c++) acc[i][j][c] = 0.f;

    h_load(sb, 0, A, B, m0, n0, 0, K, tid);
    CPA_COMMIT();

    int nkt = K >> 5;
    for (int kt = 0; kt < nkt; kt++) {
        if (kt + 1 < nkt) {
            h_load(sb, (kt + 1) & 1, A, B, m0, n0, (kt + 1) * 32, K, tid);
            CPA_COMMIT();
            CPA_WAIT1();
        } else {
            CPA_WAIT0();
        }
        __syncthreads();

        int stage = kt & 1;
        const uint32_t* sa = (const uint32_t*)(smem + stage * HBUF);
        const uint32_t* sw = (const uint32_t*)(smem + stage * HBUF + 10240);
        #pragma unroll
        for (int ks = 0; ks < 2; ks++) {          // two k16 steps per 32-half tile
            uint32_t a[2][4];
            #pragma unroll
            for (int i = 0; i < 2; i++) {
                int r0 = wm * 32 + i * 16 + tq;
                int kb = ks * 8 + tr;
                a[i][0] = sa[r0 * HSTR + kb];
                a[i][1] = sa[(r0 + 8) * HSTR + kb];
                a[i][2] = sa[r0 * HSTR + kb + 4];
                a[i][3] = sa[(r0 + 8) * HSTR + kb + 4];
            }
            #pragma unroll
            for (int j = 0; j < 8; j++) {
                int nn = wn * 64 + j * 8 + tq;
                const uint32_t* bp = sw + nn * HSTR + ks * 8 + tr;
                uint32_t b0 = bp[0], b1 = bp[4];
                mma16(acc[0][j], a[0], b0, b1);
                mma16(acc[1][j], a[1], b0, b1);
            }
        }
        __syncthreads();
    }

    #pragma unroll
    for (int i = 0; i < 2; i++) {
        #pragma unroll
        for (int half = 0; half < 2; half++) {
            int m = m0 + wm * 32 + i * 16 + tq + half * 8;
            float* orow = C + (size_t)m * N + n0;
            #pragma unroll
            for (int j = 0; j < 8; j++) {
                int nl = wn * 64 + j * 8 + tr * 2;
                float2 v = make_float2(acc[i][j][half * 2], acc[i][j][half * 2 + 1]);
                *(float2*)(orow + nl) = v;
            }
        }
    }
}

// ==================== Kernel 2: pointwise epilogue (raw -> du, gh) ==========
__device__ __forceinline__ void epi_one(float raw, float gp, float mp, float dpv,
                                        float bd, float al, float sl,
                                        float2* du, float2* gh) {
    float gate = 1.f / (1.f + __expf(-gp));
    float mod  = tanhf(mp);
    float z = dpv + bd;
    float Aa = -__expf(al);
    float splus = (z > 15.f) ? z : log1pf(__expf(z));
    float decay = __expf(splus * Aa);
    float u = (1.f - decay) * gate * tanhf(raw);
    float gl = 0.5f * raw * (1.f + erff(raw * 0.7071067811865475f));
    float sw = 1.f / (1.f + __expf(-sl));
    float opm = 1.f + mod;
    *du = make_float2(decay, u);
    *gh = make_float2((1.f - sw) * gl * opm, sw * opm);
}

__global__ void __launch_bounds__(256)
epi_kernel(const float* __restrict__ bdel, const float* __restrict__ Alog,
           const float* __restrict__ swl) {
    int idx = blockIdx.x * 256 + threadIdx.x;   // 8192*4096/4 granules
    int m  = idx >> 10;
    int n  = (idx & 1023) << 2;
    const float* rowp = g_raw + (size_t)m * 16384;
    float4 raw = *(const float4*)(rowp + n);
    float4 gp  = *(const float4*)(rowp + 4096 + n);
    float4 mp  = *(const float4*)(rowp + 8192 + n);
    float4 dp  = *(const float4*)(rowp + 12288 + n);
    float4 bd  = *(const float4*)(bdel + n);
    float4 al  = *(const float4*)(Alog + n);
    float4 sl  = *(const float4*)(swl + n);
    size_t o = (size_t)m * DN + n;
    float2 du0, gh0, du1, gh1, du2, gh2, du3, gh3;
    epi_one(raw.x, gp.x, mp.x, dp.x, bd.x, al.x, sl.x, &du0, &gh0);
    epi_one(raw.y, gp.y, mp.y, dp.y, bd.y, al.y, sl.y, &du1, &gh1);
    epi_one(raw.z, gp.z, mp.z, dp.z, bd.z, al.z, sl.z, &du2, &gh2);
    epi_one(raw.w, gp.w, mp.w, dp.w, bd.w, al.w, sl.w, &du3, &gh3);
    float4* pdu = (float4*)(g_du + o);
    float4* pgh = (float4*)(g_gh + o);
    pdu[0] = make_float4(du0.x, du0.y, du1.x, du1.y);
    pdu[1] = make_float4(du2.x, du2.y, du3.x, du3.y);
    pgh[0] = make_float4(gh0.x, gh0.y, gh1.x, gh1.y);
    pgh[1] = make_float4(gh2.x, gh2.y, gh3.x, gh3.y);
}

// ==================== Kernel 3: chunked parallel scan =======================
// 256 blocks x 1024 thr. Block: 32 channels (lanes) x 32 time-chunks (warps),
// chunk = 128 steps. Affine summary (P,U), smem carry scan, replay pass.
__global__ void __launch_bounds__(1024)
scan_kernel(const float* __restrict__ st_in, float* __restrict__ st_out, int write_state) {
    __shared__ float sP[1024], sU[1024], sC[1024];
    int tid = threadIdx.x;
    int w = tid >> 5, lane = tid & 31;
    int ch0 = blockIdx.x * 32;
    int ch = ch0 + lane;
    int batch = ch >> 12;
    int n = ch & 4095;
    size_t base = ((size_t)batch * TT) * DN + n + (size_t)w * 128 * DN;

    // pass A: per-chunk affine summary
    const float2* pdu = g_du + base;
    float P = 1.f, U = 0.f;
    #pragma unroll 8
    for (int t = 0; t < 128; t++) {
        float2 v = pdu[(size_t)t * DN];
        U = fmaf(v.x, U, v.y);
        P *= v.x;
    }
    sP[w * 32 + lane] = P;
    sU[w * 32 + lane] = U;
    __syncthreads();

    // carry scan across 32 chunks per channel (one lane per channel)
    if (tid < 32) {
        float s = st_in[ch0 + tid];
        #pragma unroll
        for (int k = 0; k < 32; k++) {
            sC[k * 32 + tid] = s;
            s = fmaf(sP[k * 32 + tid], s, sU[k * 32 + tid]);
        }
        if (write_state) st_out[ch0 + tid] = s;
    }
    __syncthreads();

    // pass B: replay with carry-in, emit y (fp16)
    float s = sC[w * 32 + lane];
    const float2* pgh = g_gh + base;
    __half* py = g_yh + base;
    #pragma unroll 4
    for (int t = 0; t < 128; t++) {
        float2 v  = pdu[(size_t)t * DN];
        float2 gh = pgh[(size_t)t * DN];
        s = fmaf(v.x, s, v.y);
        py[(size_t)t * DN] = __float2half_rn(fmaf(gh.y, s, gh.x));
    }
}

// ==================== launch ================================================
extern "C" void kernel_launch(void* const* d_in, const int* in_sizes, int n_in,
                              void* d_out, int out_size) {
    const float* x    = (const float*)d_in[0];
    const float* st   = (const float*)d_in[1];
    const float* Wm   = (const float*)d_in[2];
    const float* Wg   = (const float*)d_in[3];
    const float* Wmod = (const float*)d_in[4];
    const float* Wout = (const float*)d_in[5];
    const float* Wd   = (const float*)d_in[6];
    const float* bdel = (const float*)d_in[7];
    const float* Alog = (const float*)d_in[8];
    const float* swl  = (const float*)d_in[9];
    float* out = (float*)d_out;

    cudaFuncSetAttribute(gemm_kernel, cudaFuncAttributeMaxDynamicSharedMemorySize, HSMEM);

    static __half* p_xh = nullptr;
    static __half* p_wh = nullptr;
    static __half* p_wouth = nullptr;
    static __half* p_yh = nullptr;
    static float*  p_raw = nullptr;
    if (!p_xh) {
        void* tmp;
        cudaGetSymbolAddress(&tmp, g_xh);    p_xh = (__half*)tmp;
        cudaGetSymbolAddress(&tmp, g_wh);    p_wh = (__half*)tmp;
        cudaGetSymbolAddress(&tmp, g_wouth); p_wouth = (__half*)tmp;
        cudaGetSymbolAddress(&tmp, g_yh);    p_yh = (__half*)tmp;
        cudaGetSymbolAddress(&tmp, g_raw);   p_raw = (float*)tmp;
    }

    prepass_kernel<<<28672, 256>>>(x, Wm, Wg, Wmod, Wd, Wout);

    // proj: raw[8192,16384] = Xh[8192,1024] @ Wcat[16384,1024]^T
    gemm_kernel<<<dim3(128, 64), 256, HSMEM>>>(p_xh, p_wh, p_raw, 1024, 16384);

    epi_kernel<<<32768, 256>>>(bdel, Alog, swl);

    int has_state = (out_size >= MTOT * DM + BB * DN) ? 1 : 0;
    scan_kernel<<<256, 1024>>>(st, out + (size_t)MTOT * DM, has_state);

    // out[8192,1024] = yh[8192,4096] @ Wouth[1024,4096]^T
    gemm_kernel<<<dim3(8, 64), 256, HSMEM>>>(p_yh, p_wouth, out, 4096, 1024);
}

// round 9
// speedup vs baseline: 1.6608x; 1.0164x over previous
#include <cuda_runtime.h>
#include <cuda_fp16.h>
#include <cstdint>

#define DM 1024
#define DN 4096
#define BB 2
#define TT 4096
#define MTOT 8192   // BB*TT

// ---------------- scratch (device globals) ----------------------------------
__device__ __half  g_xh[8388608];      // fp16 X [8192,1024]
__device__ __half  g_wh[16777216];     // fp16 W_cat [16384,1024]
__device__ __half  g_wouth[4194304];   // fp16 W_out [1024,4096]
__device__ float2  g_du[33554432];     // {decay, update} [8192,4096]
__device__ float2  g_gh[33554432];     // {g, h}          [8192,4096]
__device__ __half  g_yh[33554432];     // fp16 y          [8192,4096]

// ---------------- helpers ----------------------------------------------------
__device__ __forceinline__ uint32_t smem_u32(const void* p) {
    uint32_t a;
    asm("{ .reg .u64 t; cvta.to.shared.u64 t, %1; cvt.u32.u64 %0, t; }" : "=r"(a) : "l"(p));
    return a;
}

#define CPA16(dst, src) asm volatile("cp.async.cg.shared.global [%0], [%1], 16;" :: "r"(dst), "l"(src) : "memory")
#define CPA_COMMIT()    asm volatile("cp.async.commit_group;" ::: "memory")
#define CPA_WAIT0()     asm volatile("cp.async.wait_group 0;" ::: "memory")
#define CPA_WAIT1()     asm volatile("cp.async.wait_group 1;" ::: "memory")

// m16n8k16 fp16 mma, fp32 accum
__device__ __forceinline__ void mma16(float* c, const uint32_t* a, uint32_t b0, uint32_t b1) {
    asm volatile("mma.sync.aligned.m16n8k16.row.col.f32.f16.f16.f32 "
                 "{%0,%1,%2,%3}, {%4,%5,%6,%7}, {%8,%9}, {%0,%1,%2,%3};"
                 : "+f"(c[0]), "+f"(c[1]), "+f"(c[2]), "+f"(c[3])
                 : "r"(a[0]), "r"(a[1]), "r"(a[2]), "r"(a[3]), "r"(b0), "r"(b1));
}

// ==================== Kernel 0: fp32 -> fp16 conversion =====================
__global__ void __launch_bounds__(256)
prepass_kernel(const float* __restrict__ X,
               const float* __restrict__ Wm, const float* __restrict__ Wg,
               const float* __restrict__ Wmod, const float* __restrict__ Wd,
               const float* __restrict__ Wout) {
    int idx = blockIdx.x * 256 + threadIdx.x;
    const float4* src;
    __half2* dst;
    if (idx < 2097152) {
        src = (const float4*)X + idx;
        dst = (__half2*)g_xh + idx * 2;
    } else if (idx < 6291456) {
        int t = idx - 2097152;
        int w = t >> 20;
        int o = t & 1048575;
        const float* W = (w == 0) ? Wm : (w == 1) ? Wg : (w == 2) ? Wmod : Wd;
        src = (const float4*)W + o;
        dst = (__half2*)g_wh + ((size_t)w * 1048576 + o) * 2;
    } else {
        int o = idx - 6291456;
        src = (const float4*)Wout + o;
        dst = (__half2*)g_wouth + o * 2;
    }
    float4 v = *src;
    dst[0] = __floats2half2_rn(v.x, v.y);
    dst[1] = __floats2half2_rn(v.z, v.w);
}

// ---------------- shared epilogue math ---------------------------------------
__device__ __forceinline__ void epi_one(float raw, float gp, float mp, float dpv,
                                        float bd, float al, float sl,
                                        float2* du, float2* gh) {
    float gate = 1.f / (1.f + __expf(-gp));
    float mod  = tanhf(mp);
    float z = dpv + bd;
    float Aa = -__expf(al);
    float splus = (z > 15.f) ? z : log1pf(__expf(z));
    float decay = __expf(splus * Aa);
    float u = (1.f - decay) * gate * tanhf(raw);
    float gl = 0.5f * raw * (1.f + erff(raw * 0.7071067811865475f));
    float sw = 1.f / (1.f + __expf(-sl));
    float opm = 1.f + mod;
    *du = make_float2(decay, u);
    *gh = make_float2((1.f - sw) * gl * opm, sw * opm);
}

// ==================== Kernel 1: fused 4-weight proj GEMM + epilogue =========
// CTA 256 thr (8 warps: 4m x 2n). Tile 128m x 64n x 4 weights. KT=32 halves.
// SMEM/stage: A 128x80B (10240) + B 256x80B (20480) = 30720; x2 = 61440 B.
#define HSTR   20
#define FBUF   30720
#define FSMEM  (2 * FBUF)

__device__ __forceinline__ void f_load(uint32_t sb, int stage, int m0, int n0, int k0, int tid) {
    uint32_t base = sb + stage * FBUF;
    #pragma unroll
    for (int i = 0; i < 2; i++) {                 // A: 512 16B-chunks
        int ch = tid + i * 256;
        int r = ch >> 2, c = ch & 3;
        CPA16(base + r * 80 + c * 16, g_xh + (size_t)(m0 + r) * 1024 + k0 + c * 8);
    }
    #pragma unroll
    for (int i = 0; i < 4; i++) {                 // B: 1024 16B-chunks (4 weights)
        int ch = tid + i * 256;
        int r = ch >> 2, c = ch & 3;              // r in 0..255
        int w = r >> 6, rr = r & 63;
        CPA16(base + 10240 + r * 80 + c * 16,
              g_wh + ((size_t)w * 4096 + n0 + rr) * 1024 + k0 + c * 8);
    }
}

__global__ void __launch_bounds__(256, 1)
proj_fused_kernel(const float* __restrict__ bdel, const float* __restrict__ Alog,
                  const float* __restrict__ swl) {
    extern __shared__ char smem[];
    uint32_t sb = smem_u32(smem);
    int tid = threadIdx.x, wid = tid >> 5, lane = tid & 31;
    int wm = wid & 3, wn = wid >> 2;
    int tq = lane >> 2, tr = lane & 3;
    int m0 = blockIdx.y * 128;
    int n0 = blockIdx.x * 64;

    float acc[4][2][4][4];
    #pragma unroll
    for (int w = 0; w < 4; w++)
        #pragma unroll
        for (int i = 0; i < 2; i++)
            #pragma unroll
            for (int j = 0; j < 4; j++)
                #pragma unroll
                for (int c = 0; c < 4; c++) acc[w][i][j][c] = 0.f;

    f_load(sb, 0, m0, n0, 0, tid);
    CPA_COMMIT();

    for (int kt = 0; kt < 32; kt++) {
        if (kt + 1 < 32) {
            f_load(sb, (kt + 1) & 1, m0, n0, (kt + 1) * 32, tid);
            CPA_COMMIT();
            CPA_WAIT1();
        } else {
            CPA_WAIT0();
        }
        __syncthreads();

        int stage = kt & 1;
        const uint32_t* sa = (const uint32_t*)(smem + stage * FBUF);
        const uint32_t* sw = (const uint32_t*)(smem + stage * FBUF + 10240);
        #pragma unroll
        for (int ks = 0; ks < 2; ks++) {
            uint32_t a[2][4];
            #pragma unroll
            for (int i = 0; i < 2; i++) {
                int r0 = wm * 32 + i * 16 + tq;
                int kb = ks * 8 + tr;
                a[i][0] = sa[r0 * HSTR + kb];
                a[i][1] = sa[(r0 + 8) * HSTR + kb];
                a[i][2] = sa[r0 * HSTR + kb + 4];
                a[i][3] = sa[(r0 + 8) * HSTR + kb + 4];
            }
            #pragma unroll
            for (int w = 0; w < 4; w++) {
                #pragma unroll
                for (int j = 0; j < 4; j++) {
                    int nn = w * 64 + wn * 32 + j * 8 + tq;
                    const uint32_t* bp = sw + nn * HSTR + ks * 8 + tr;
                    uint32_t b0 = bp[0], b1 = bp[4];
                    mma16(acc[w][0][j], a[0], b0, b1);
                    mma16(acc[w][1][j], a[1], b0, b1);
                }
            }
        }
        __syncthreads();
    }

    // ---- fused pointwise epilogue -> g_du, g_gh ----
    float bdv[8], alv[8], slv[8];
    #pragma unroll
    for (int j = 0; j < 4; j++)
        #pragma unroll
        for (int cc = 0; cc < 2; cc++) {
            int n = n0 + wn * 32 + j * 8 + tr * 2 + cc;
            bdv[j * 2 + cc] = __ldg(bdel + n);
            alv[j * 2 + cc] = __ldg(Alog + n);
            slv[j * 2 + cc] = __ldg(swl + n);
        }

    #pragma unroll
    for (int i = 0; i < 2; i++) {
        #pragma unroll
        for (int half = 0; half < 2; half++) {
            int m = m0 + wm * 32 + i * 16 + tq + half * 8;
            size_t rowo = (size_t)m * DN + n0;
            #pragma unroll
            for (int j = 0; j < 4; j++) {
                #pragma unroll
                for (int cc = 0; cc < 2; cc++) {
                    int ci = half * 2 + cc;
                    int e = j * 2 + cc;
                    int nl = wn * 32 + j * 8 + tr * 2 + cc;
                    float2 du, gh;
                    epi_one(acc[0][i][j][ci], acc[1][i][j][ci],
                            acc[2][i][j][ci], acc[3][i][j][ci],
                            bdv[e], alv[e], slv[e], &du, &gh);
                    g_du[rowo + nl] = du;
                    g_gh[rowo + nl] = gh;
                }
            }
        }
    }
}

// ==================== fp16 GEMM (for output projection) =====================
// CTA 256 thr (8 warps: 4m x 2n), tile 128m x 128n, warp 32x64, KT=32 halves.
#define HBUF  20480
#define HSMEM (2 * HBUF)

__device__ __forceinline__ void h_load(uint32_t sb, int stage,
                                       const __half* __restrict__ A,
                                       const __half* __restrict__ B,
                                       int m0, int n0, int k0, int K, int tid) {
    uint32_t base = sb + stage * HBUF;
    #pragma unroll
    for (int i = 0; i < 2; i++) {
        int ch = tid + i * 256;
        int r = ch >> 2, c = ch & 3;
        CPA16(base + r * 80 + c * 16, A + (size_t)(m0 + r) * K + k0 + c * 8);
    }
    #pragma unroll
    for (int i = 0; i < 2; i++) {
        int ch = tid + i * 256;
        int r = ch >> 2, c = ch & 3;
        CPA16(base + 10240 + r * 80 + c * 16, B + (size_t)(n0 + r) * K + k0 + c * 8);
    }
}

__global__ void __launch_bounds__(256, 2)
gemm_kernel(const __half* __restrict__ A, const __half* __restrict__ B,
            float* __restrict__ C, int K, int N) {
    extern __shared__ char smem[];
    uint32_t sb = smem_u32(smem);
    int tid = threadIdx.x, wid = tid >> 5, lane = tid & 31;
    int wm = wid & 3, wn = wid >> 2;
    int tq = lane >> 2, tr = lane & 3;
    int m0 = blockIdx.y * 128;
    int n0 = blockIdx.x * 128;

    float acc[2][8][4];
    #pragma unroll
    for (int i = 0; i < 2; i++)
        #pragma unroll
        for (int j = 0; j < 8; j++)
            #pragma unroll
            for (int c = 0; c < 4; c++) acc[i][j][c] = 0.f;

    h_load(sb, 0, A, B, m0, n0, 0, K, tid);
    CPA_COMMIT();

    int nkt = K >> 5;
    for (int kt = 0; kt < nkt; kt++) {
        if (kt + 1 < nkt) {
            h_load(sb, (kt + 1) & 1, A, B, m0, n0, (kt + 1) * 32, K, tid);
            CPA_COMMIT();
            CPA_WAIT1();
        } else {
            CPA_WAIT0();
        }
        __syncthreads();

        int stage = kt & 1;
        const uint32_t* sa = (const uint32_t*)(smem + stage * HBUF);
        const uint32_t* sw = (const uint32_t*)(smem + stage * HBUF + 10240);
        #pragma unroll
        for (int ks = 0; ks < 2; ks++) {
            uint32_t a[2][4];
            #pragma unroll
            for (int i = 0; i < 2; i++) {
                int r0 = wm * 32 + i * 16 + tq;
                int kb = ks * 8 + tr;
                a[i][0] = sa[r0 * HSTR + kb];
                a[i][1] = sa[(r0 + 8) * HSTR + kb];
                a[i][2] = sa[r0 * HSTR + kb + 4];
                a[i][3] = sa[(r0 + 8) * HSTR + kb + 4];
            }
            #pragma unroll
            for (int j = 0; j < 8; j++) {
                int nn = wn * 64 + j * 8 + tq;
                const uint32_t* bp = sw + nn * HSTR + ks * 8 + tr;
                uint32_t b0 = bp[0], b1 = bp[4];
                mma16(acc[0][j], a[0], b0, b1);
                mma16(acc[1][j], a[1], b0, b1);
            }
        }
        __syncthreads();
    }

    #pragma unroll
    for (int i = 0; i < 2; i++) {
        #pragma unroll
        for (int half = 0; half < 2; half++) {
            int m = m0 + wm * 32 + i * 16 + tq + half * 8;
            float* orow = C + (size_t)m * N + n0;
            #pragma unroll
            for (int j = 0; j < 8; j++) {
                int nl = wn * 64 + j * 8 + tr * 2;
                float2 v = make_float2(acc[i][j][half * 2], acc[i][j][half * 2 + 1]);
                *(float2*)(orow + nl) = v;
            }
        }
    }
}

// ==================== Kernel 3: chunked parallel scan =======================
__global__ void __launch_bounds__(1024)
scan_kernel(const float* __restrict__ st_in, float* __restrict__ st_out, int write_state) {
    __shared__ float sP[1024], sU[1024], sC[1024];
    int tid = threadIdx.x;
    int w = tid >> 5, lane = tid & 31;
    int ch0 = blockIdx.x * 32;
    int ch = ch0 + lane;
    int batch = ch >> 12;
    int n = ch & 4095;
    size_t base = ((size_t)batch * TT) * DN + n + (size_t)w * 128 * DN;

    const float2* pdu = g_du + base;
    float P = 1.f, U = 0.f;
    #pragma unroll 8
    for (int t = 0; t < 128; t++) {
        float2 v = pdu[(size_t)t * DN];
        U = fmaf(v.x, U, v.y);
        P *= v.x;
    }
    sP[w * 32 + lane] = P;
    sU[w * 32 + lane] = U;
    __syncthreads();

    if (tid < 32) {
        float s = st_in[ch0 + tid];
        #pragma unroll
        for (int k = 0; k < 32; k++) {
            sC[k * 32 + tid] = s;
            s = fmaf(sP[k * 32 + tid], s, sU[k * 32 + tid]);
        }
        if (write_state) st_out[ch0 + tid] = s;
    }
    __syncthreads();

    float s = sC[w * 32 + lane];
    const float2* pgh = g_gh + base;
    __half* py = g_yh + base;
    #pragma unroll 4
    for (int t = 0; t < 128; t++) {
        float2 v  = pdu[(size_t)t * DN];
        float2 gh = pgh[(size_t)t * DN];
        s = fmaf(v.x, s, v.y);
        py[(size_t)t * DN] = __float2half_rn(fmaf(gh.y, s, gh.x));
    }
}

// ==================== launch ================================================
extern "C" void kernel_launch(void* const* d_in, const int* in_sizes, int n_in,
                              void* d_out, int out_size) {
    const float* x    = (const float*)d_in[0];
    const float* st   = (const float*)d_in[1];
    const float* Wm   = (const float*)d_in[2];
    const float* Wg   = (const float*)d_in[3];
    const float* Wmod = (const float*)d_in[4];
    const float* Wout = (const float*)d_in[5];
    const float* Wd   = (const float*)d_in[6];
    const float* bdel = (const float*)d_in[7];
    const float* Alog = (const float*)d_in[8];
    const float* swl  = (const float*)d_in[9];
    float* out = (float*)d_out;

    cudaFuncSetAttribute(proj_fused_kernel, cudaFuncAttributeMaxDynamicSharedMemorySize, FSMEM);
    cudaFuncSetAttribute(gemm_kernel, cudaFuncAttributeMaxDynamicSharedMemorySize, HSMEM);

    static __half* p_yh = nullptr;
    static __half* p_wouth = nullptr;
    if (!p_yh) {
        void* tmp;
        cudaGetSymbolAddress(&tmp, g_yh);    p_yh = (__half*)tmp;
        cudaGetSymbolAddress(&tmp, g_wouth); p_wouth = (__half*)tmp;
    }

    prepass_kernel<<<28672, 256>>>(x, Wm, Wg, Wmod, Wd, Wout);

    // fused proj: du/gh[8192,4096] from Xh @ Wcat^T (4 weights per CTA)
    proj_fused_kernel<<<dim3(64, 64), 256, FSMEM>>>(bdel, Alog, swl);

    int has_state = (out_size >= MTOT * DM + BB * DN) ? 1 : 0;
    scan_kernel<<<256, 1024>>>(st, out + (size_t)MTOT * DM, has_state);

    // out[8192,1024] = yh[8192,4096] @ Wouth[1024,4096]^T
    gemm_kernel<<<dim3(8, 64), 256, HSMEM>>>(p_yh, p_wouth, out, 4096, 1024);
}